// round 13
// baseline (speedup 1.0000x reference)
#include <cuda_runtime.h>
#include <cuda_fp16.h>
#include <mma.h>

using namespace nvcuda;

#define NN 50000
#define EE 1600000
#define DD 128
#define GEMM_BLKS 391           // ceil(50000/128)
#define SPMM_BLKS 6250          // ceil(50000/8)
#define SCAN_BLKS 196           // ceil(50000/256)
#define SLDA 136                // smem leading dim (halves / floats)

// ---------------- scratch (static device memory, allocation-free) ------------
__device__ __align__(16) int      g_degi[NN];
__device__ __align__(16) int      g_fill[NN];
__device__ __align__(16) int      g_rowptr[NN + 1];
__device__ __align__(16) float    g_dinv[NN];
__device__ __align__(16) int      g_part[256];
__device__ __align__(16) unsigned g_csrp[EE];       // low16 = src, high16 = fp16 weight
__device__ __align__(16) __half   g_f16[(long)NN * DD];
__device__ __align__(16) __half   g_p1[(long)NN * DD];
__device__ __align__(16) __half   g_p2[(long)NN * DD];
__device__ __align__(16) __half   g_p3[(long)NN * DD];
__device__ __align__(16) float    g_acc[(long)NN * DD];
__device__ __align__(16) __half   g_Whi[13 * DD * DD];

// ---------------- setup kernels -----------------------------------------------
__global__ void k_zero2(int* __restrict__ a, int* __restrict__ b) {
    int i = blockIdx.x * blockDim.x + threadIdx.x;
    if (i < NN) { a[i] = 0; b[i] = 0; }
}

__global__ void k_deg(const int* __restrict__ col) {
    int e = blockIdx.x * blockDim.x + threadIdx.x;
    if (e < EE) atomicAdd(&g_degi[col[e]], 1);
}

// x -> fp16 plane + all weights -> fp16 (runs on s1, parallel to deg/scan)
__global__ void k_cvt(const float* __restrict__ x,
                      const float* __restrict__ W1, const float* __restrict__ W2,
                      const float* __restrict__ W3, const float* __restrict__ Wf) {
    long i = (long)blockIdx.x * blockDim.x + threadIdx.x;
    const long xtot = (long)NN * DD / 4;
    if (i < xtot) {
        float4 v = ((const float4*)x)[i];
        __half2 a = __floats2half2_rn(v.x, v.y);
        __half2 b = __floats2half2_rn(v.z, v.w);
        uint2 o;
        o.x = *(const unsigned*)&a;
        o.y = *(const unsigned*)&b;
        ((uint2*)g_f16)[i] = o;
    }
    if (i < 13 * DD * DD) {
        int m = (int)(i >> 14);
        int r = (int)(i & 16383);
        const float* src;
        if (m < 4)       src = W1 + m * 16384;
        else if (m < 8)  src = W2 + (m - 4) * 16384;
        else if (m < 12) src = W3 + (m - 8) * 16384;
        else             src = Wf;
        g_Whi[i] = __float2half_rn(src[r]);
    }
}

__global__ void k_blocksum() {
    __shared__ int wsum[8];
    int tid = threadIdx.x, lane = tid & 31, wid = tid >> 5;
    int idx = blockIdx.x * 256 + tid;
    int v = (idx < NN) ? g_degi[idx] : 0;
#pragma unroll
    for (int o = 16; o > 0; o >>= 1) v += __shfl_down_sync(0xffffffffu, v, o);
    if (lane == 0) wsum[wid] = v;
    __syncthreads();
    if (tid == 0) {
        int s = 0;
#pragma unroll
        for (int w = 0; w < 8; w++) s += wsum[w];
        g_part[blockIdx.x] = s;
    }
}

__global__ void k_scanpart() {
    __shared__ int wsum[8];
    int tid = threadIdx.x, lane = tid & 31, wid = tid >> 5;
    int v = (tid < SCAN_BLKS) ? g_part[tid] : 0;
    int incl = v;
#pragma unroll
    for (int o = 1; o < 32; o <<= 1) {
        int t = __shfl_up_sync(0xffffffffu, incl, o);
        if (lane >= o) incl += t;
    }
    if (lane == 31) wsum[wid] = incl;
    __syncthreads();
    if (wid == 0 && lane < 8) {
        int t = wsum[lane];
        int ti = t;
#pragma unroll
        for (int o = 1; o < 8; o <<= 1) {
            int u = __shfl_up_sync(0xffu, ti, o);
            if (lane >= o) ti += u;
        }
        wsum[lane] = ti - t;
    }
    __syncthreads();
    if (tid < SCAN_BLKS) g_part[tid] = wsum[wid] + incl - v;
}

__global__ void k_scanfinal() {
    __shared__ int wsum[8];
    int tid = threadIdx.x, lane = tid & 31, wid = tid >> 5;
    int idx = blockIdx.x * 256 + tid;
    int v = (idx < NN) ? g_degi[idx] : 0;
    int incl = v;
#pragma unroll
    for (int o = 1; o < 32; o <<= 1) {
        int t = __shfl_up_sync(0xffffffffu, incl, o);
        if (lane >= o) incl += t;
    }
    if (lane == 31) wsum[wid] = incl;
    __syncthreads();
    if (wid == 0 && lane < 8) {
        int t = wsum[lane];
        int ti = t;
#pragma unroll
        for (int o = 1; o < 8; o <<= 1) {
            int u = __shfl_up_sync(0xffu, ti, o);
            if (lane >= o) ti += u;
        }
        wsum[lane] = ti - t;
    }
    __syncthreads();
    int excl = g_part[blockIdx.x] + wsum[wid] + incl - v;
    if (idx < NN) {
        g_rowptr[idx] = excl;
        g_dinv[idx] = v > 0 ? rsqrtf((float)v) : 0.f;
    }
    if (blockIdx.x == SCAN_BLKS - 1 && tid == 255) g_rowptr[NN] = excl + v;
}

__global__ void k_fill(const int* __restrict__ row, const int* __restrict__ col) {
    int e = blockIdx.x * blockDim.x + threadIdx.x;
    if (e >= EE) return;
    int s = row[e], c = col[e];
    int p = atomicAdd(&g_fill[c], 1) + g_rowptr[c];
    float w = g_dinv[s] * g_dinv[c];
    g_csrp[p] = (unsigned)s |
                ((unsigned)__half_as_ushort(__float2half_rn(w)) << 16);
}

// ---------------- SpMM fp16 packed-CSR ---------------------------------------
__device__ __forceinline__ float csr_w(unsigned c) {
    return __half2float(__ushort_as_half((unsigned short)(c >> 16)));
}

__global__ void __launch_bounds__(256)
k_spmm16(const __half* __restrict__ cur, __half* __restrict__ outp) {
    int node = blockIdx.x * 8 + (threadIdx.x >> 5);
    if (node >= NN) return;
    int lane = threadIdx.x & 31;
    int s = __ldg(&g_rowptr[node]);
    int e = __ldg(&g_rowptr[node + 1]);

    float4 acc = make_float4(0.f, 0.f, 0.f, 0.f);
    int i = s;
    for (; i + 3 < e; i += 4) {
        unsigned c0 = __ldg(&g_csrp[i]);
        unsigned c1 = __ldg(&g_csrp[i + 1]);
        unsigned c2 = __ldg(&g_csrp[i + 2]);
        unsigned c3 = __ldg(&g_csrp[i + 3]);
        uint2 r0 = __ldg(((const uint2*)(cur + (long)(c0 & 0xFFFF) * DD)) + lane);
        uint2 r1 = __ldg(((const uint2*)(cur + (long)(c1 & 0xFFFF) * DD)) + lane);
        uint2 r2 = __ldg(((const uint2*)(cur + (long)(c2 & 0xFFFF) * DD)) + lane);
        uint2 r3 = __ldg(((const uint2*)(cur + (long)(c3 & 0xFFFF) * DD)) + lane);
        float w0 = csr_w(c0), w1 = csr_w(c1), w2 = csr_w(c2), w3 = csr_w(c3);
        float2 a0 = __half22float2(*(const __half2*)&r0.x);
        float2 b0 = __half22float2(*(const __half2*)&r0.y);
        float2 a1 = __half22float2(*(const __half2*)&r1.x);
        float2 b1 = __half22float2(*(const __half2*)&r1.y);
        float2 a2 = __half22float2(*(const __half2*)&r2.x);
        float2 b2 = __half22float2(*(const __half2*)&r2.y);
        float2 a3 = __half22float2(*(const __half2*)&r3.x);
        float2 b3 = __half22float2(*(const __half2*)&r3.y);
        acc.x += w0 * a0.x + w1 * a1.x + w2 * a2.x + w3 * a3.x;
        acc.y += w0 * a0.y + w1 * a1.y + w2 * a2.y + w3 * a3.y;
        acc.z += w0 * b0.x + w1 * b1.x + w2 * b2.x + w3 * b3.x;
        acc.w += w0 * b0.y + w1 * b1.y + w2 * b2.y + w3 * b3.y;
    }
    for (; i < e; i++) {
        unsigned c0 = __ldg(&g_csrp[i]);
        uint2 r0 = __ldg(((const uint2*)(cur + (long)(c0 & 0xFFFF) * DD)) + lane);
        float w0 = csr_w(c0);
        float2 a0 = __half22float2(*(const __half2*)&r0.x);
        float2 b0 = __half22float2(*(const __half2*)&r0.y);
        acc.x += w0 * a0.x;
        acc.y += w0 * a0.y;
        acc.z += w0 * b0.x;
        acc.w += w0 * b0.y;
    }
    __half2 oa = __floats2half2_rn(acc.x, acc.y);
    __half2 ob = __floats2half2_rn(acc.z, acc.w);
    uint2 o;
    o.x = *(const unsigned*)&oa;
    o.y = *(const unsigned*)&ob;
    ((uint2*)(outp + (long)node * DD))[lane] = o;
}

// ---------------- shared GEMM helpers ----------------------------------------
__device__ __forceinline__ void stage_AB(const __half* __restrict__ A,
                                         const __half* __restrict__ W,
                                         __half* As, __half* Bh, int m0, int tid) {
#pragma unroll
    for (int it = 0; it < 8; it++) {
        int idx = it * 256 + tid;
        int row = idx >> 4;
        int c8 = (idx & 15) << 3;
        uint4 v = make_uint4(0u, 0u, 0u, 0u);
        if (m0 + row < NN) v = *(const uint4*)(A + (long)(m0 + row) * DD + c8);
        *(uint4*)(As + row * SLDA + c8) = v;
        *(uint4*)(Bh + row * SLDA + c8) = *(const uint4*)(W + row * DD + c8);
    }
}

template <typename FragAcc>
__device__ __forceinline__ void mma_tile1(const __half* As, const __half* Bh,
                                          FragAcc acc[2][4], int rw, int cw) {
#pragma unroll
    for (int k = 0; k < 8; k++) {
        wmma::fragment<wmma::matrix_a, 16, 16, 16, __half, wmma::row_major> a[2];
        wmma::load_matrix_sync(a[0], As + (rw + 0) * SLDA + k * 16, SLDA);
        wmma::load_matrix_sync(a[1], As + (rw + 16) * SLDA + k * 16, SLDA);
#pragma unroll
        for (int j = 0; j < 4; j++) {
            wmma::fragment<wmma::matrix_b, 16, 16, 16, __half, wmma::row_major> bh;
            wmma::load_matrix_sync(bh, Bh + (k * 16) * SLDA + cw + j * 16, SLDA);
#pragma unroll
            for (int i = 0; i < 2; i++)
                wmma::mma_sync(acc[i][j], a[i], bh, acc[i][j]);
        }
    }
}

// ---------------- wmma GEMM: MODE 0: C = A@W   MODE 2: f16 = relu(C+A@W+b) ---
template <int MODE>
__global__ void __launch_bounds__(256)
k_wgemm(const __half* __restrict__ A, const __half* __restrict__ W,
        float* __restrict__ C, const float* __restrict__ bias,
        __half* __restrict__ dst16) {
    extern __shared__ __align__(16) char smem_raw[];
    __half* As = (__half*)smem_raw;
    __half* Bh = As + 128 * SLDA;
    float*  Cs = (float*)smem_raw;

    int tid = threadIdx.x;
    int wid = tid >> 5;
    int m0 = blockIdx.x * 128;

    stage_AB(A, W, As, Bh, m0, tid);
    __syncthreads();

    int rw = (wid >> 1) * 32;
    int cw = (wid & 1) * 64;

    wmma::fragment<wmma::accumulator, 16, 16, 16, float> acc[2][4];
#pragma unroll
    for (int i = 0; i < 2; i++)
#pragma unroll
        for (int j = 0; j < 4; j++) wmma::fill_fragment(acc[i][j], 0.f);

    mma_tile1(As, Bh, acc, rw, cw);
    __syncthreads();

#pragma unroll
    for (int i = 0; i < 2; i++)
#pragma unroll
        for (int j = 0; j < 4; j++)
            wmma::store_matrix_sync(Cs + (rw + i * 16) * SLDA + cw + j * 16,
                                    acc[i][j], SLDA, wmma::mem_row_major);
    __syncthreads();

#pragma unroll
    for (int it = 0; it < 16; it++) {
        int q = it * 256 + tid;
        int row = q >> 5;
        int c4 = (q & 31) << 2;
        int r = m0 + row;
        if (r >= NN) continue;
        const float* cp = Cs + row * SLDA + c4;
        float4 v = make_float4(cp[0], cp[1], cp[2], cp[3]);
        if (MODE == 0) {
            *(float4*)(C + (long)r * DD + c4) = v;
        } else {
            float4 o = *(const float4*)(C + (long)r * DD + c4);
            float4 bb = *(const float4*)(bias + c4);
            v.x = fmaxf(v.x + o.x + bb.x, 0.f);
            v.y = fmaxf(v.y + o.y + bb.y, 0.f);
            v.z = fmaxf(v.z + o.z + bb.z, 0.f);
            v.w = fmaxf(v.w + o.w + bb.w, 0.f);
            __half2 ha = __floats2half2_rn(v.x, v.y);
            __half2 hb = __floats2half2_rn(v.z, v.w);
            uint2 u;
            u.x = *(const unsigned*)&ha;
            u.y = *(const unsigned*)&hb;
            *(uint2*)(dst16 + (long)r * DD + c4) = u;
        }
    }
}

// ---------------- K=256 accumulate: C += A0@W[0] + A1@W[1] -------------------
__global__ void __launch_bounds__(256)
k_wgemm12(const __half* __restrict__ A0, const __half* __restrict__ A1,
          const __half* __restrict__ W, float* __restrict__ C) {
    extern __shared__ __align__(16) char smem_raw[];
    __half* As = (__half*)smem_raw;
    __half* Bh = As + 128 * SLDA;
    float*  Cs = (float*)smem_raw;

    int tid = threadIdx.x;
    int wid = tid >> 5;
    int m0 = blockIdx.x * 128;
    int rw = (wid >> 1) * 32;
    int cw = (wid & 1) * 64;

    wmma::fragment<wmma::accumulator, 16, 16, 16, float> acc[2][4];
#pragma unroll
    for (int i = 0; i < 2; i++)
#pragma unroll
        for (int j = 0; j < 4; j++) wmma::fill_fragment(acc[i][j], 0.f);

#pragma unroll
    for (int c = 0; c < 2; c++) {
        stage_AB(c ? A1 : A0, W + c * DD * DD, As, Bh, m0, tid);
        __syncthreads();
        mma_tile1(As, Bh, acc, rw, cw);
        __syncthreads();
    }

#pragma unroll
    for (int i = 0; i < 2; i++)
#pragma unroll
        for (int j = 0; j < 4; j++)
            wmma::store_matrix_sync(Cs + (rw + i * 16) * SLDA + cw + j * 16,
                                    acc[i][j], SLDA, wmma::mem_row_major);
    __syncthreads();

#pragma unroll
    for (int it = 0; it < 16; it++) {
        int q = it * 256 + tid;
        int row = q >> 5;
        int c4 = (q & 31) << 2;
        int r = m0 + row;
        if (r >= NN) continue;
        const float* cp = Cs + row * SLDA + c4;
        float4 o = *(const float4*)(C + (long)r * DD + c4);
        o.x += cp[0]; o.y += cp[1]; o.z += cp[2]; o.w += cp[3];
        *(float4*)(C + (long)r * DD + c4) = o;
    }
}

// ---------------- fused layer-3 epilogue + final GEMM ------------------------
// t = relu(acc + p3@W3 + b3) ; out = t @ Wf + bf
__global__ void __launch_bounds__(256)
k_wfin(const __half* __restrict__ p3, const __half* __restrict__ W3,
       const float* __restrict__ accg, const float* __restrict__ b3,
       const __half* __restrict__ Wf, const float* __restrict__ bf,
       float* __restrict__ outp) {
    extern __shared__ __align__(16) char smem_raw[];
    __half* As = (__half*)smem_raw;                       // region0 A tile
    __half* Bh = As + 128 * SLDA;                         // region0 B tile
    float*  Cs = (float*)(smem_raw + 2 * 128 * SLDA * 2); // region1 (69632 off)

    int tid = threadIdx.x;
    int wid = tid >> 5;
    int m0 = blockIdx.x * 128;
    int rw = (wid >> 1) * 32;
    int cw = (wid & 1) * 64;

    wmma::fragment<wmma::accumulator, 16, 16, 16, float> acc[2][4];

    // --- stage 1: p3 @ W3 ---
    stage_AB(p3, W3, As, Bh, m0, tid);
    __syncthreads();
#pragma unroll
    for (int i = 0; i < 2; i++)
#pragma unroll
        for (int j = 0; j < 4; j++) wmma::fill_fragment(acc[i][j], 0.f);
    mma_tile1(As, Bh, acc, rw, cw);
#pragma unroll
    for (int i = 0; i < 2; i++)
#pragma unroll
        for (int j = 0; j < 4; j++)
            wmma::store_matrix_sync(Cs + (rw + i * 16) * SLDA + cw + j * 16,
                                    acc[i][j], SLDA, wmma::mem_row_major);
    __syncthreads();   // all MMA1 + Cs stores done; As/Bh free for reuse

    // --- epilogue to fp16 tile in As ---
#pragma unroll
    for (int it = 0; it < 16; it++) {
        int q = it * 256 + tid;
        int row = q >> 5;
        int c4 = (q & 31) << 2;
        int r = m0 + row;
        float4 v = make_float4(0.f, 0.f, 0.f, 0.f);
        if (r < NN) {
            const float* cp = Cs + row * SLDA + c4;
            float4 o = *(const float4*)(accg + (long)r * DD + c4);
            float4 bb = *(const float4*)(b3 + c4);
            v.x = fmaxf(cp[0] + o.x + bb.x, 0.f);
            v.y = fmaxf(cp[1] + o.y + bb.y, 0.f);
            v.z = fmaxf(cp[2] + o.z + bb.z, 0.f);
            v.w = fmaxf(cp[3] + o.w + bb.w, 0.f);
        }
        __half2 ha = __floats2half2_rn(v.x, v.y);
        __half2 hb = __floats2half2_rn(v.z, v.w);
        uint2 u;
        u.x = *(const unsigned*)&ha;
        u.y = *(const unsigned*)&hb;
        *(uint2*)(As + row * SLDA + c4) = u;
    }
    // stage Wf into Bh
#pragma unroll
    for (int it = 0; it < 8; it++) {
        int idx = it * 256 + tid;
        int row = idx >> 4;
        int c8 = (idx & 15) << 3;
        *(uint4*)(Bh + row * SLDA + c8) = *(const uint4*)(Wf + row * DD + c8);
    }
    __syncthreads();

    // --- stage 2: t @ Wf ---
#pragma unroll
    for (int i = 0; i < 2; i++)
#pragma unroll
        for (int j = 0; j < 4; j++) wmma::fill_fragment(acc[i][j], 0.f);
    mma_tile1(As, Bh, acc, rw, cw);
#pragma unroll
    for (int i = 0; i < 2; i++)
#pragma unroll
        for (int j = 0; j < 4; j++)
            wmma::store_matrix_sync(Cs + (rw + i * 16) * SLDA + cw + j * 16,
                                    acc[i][j], SLDA, wmma::mem_row_major);
    __syncthreads();

#pragma unroll
    for (int it = 0; it < 16; it++) {
        int q = it * 256 + tid;
        int row = q >> 5;
        int c4 = (q & 31) << 2;
        int r = m0 + row;
        if (r >= NN) continue;
        const float* cp = Cs + row * SLDA + c4;
        float4 bb = *(const float4*)(bf + c4);
        float4 v = make_float4(cp[0] + bb.x, cp[1] + bb.y,
                               cp[2] + bb.z, cp[3] + bb.w);
        *(float4*)(outp + (long)r * DD + c4) = v;
    }
}

// ---------------- stream/event resources (built once, outside capture) -------
struct OverlapRes {
    cudaStream_t s1;
    cudaEvent_t ev[16];
    OverlapRes() {
        cudaStreamCreateWithFlags(&s1, cudaStreamNonBlocking);
        for (int i = 0; i < 16; i++)
            cudaEventCreateWithFlags(&ev[i], cudaEventDisableTiming);
    }
};

// ---------------- host orchestration -----------------------------------------
extern "C" void kernel_launch(void* const* d_in, const int* in_sizes, int n_in,
                              void* d_out, int out_size) {
    static OverlapRes R;  // created on first (uncaptured) correctness call

    const float* x  = (const float*)d_in[0];
    const int*   ei = (const int*)d_in[1];
    const float* W1 = (const float*)d_in[2];
    const float* b1 = (const float*)d_in[3];
    const float* W2 = (const float*)d_in[4];
    const float* b2 = (const float*)d_in[5];
    const float* W3 = (const float*)d_in[6];
    const float* b3 = (const float*)d_in[7];
    const float* Wf = (const float*)d_in[8];
    const float* bf = (const float*)d_in[9];
    float* out = (float*)d_out;

    const int* row = ei;
    const int* col = ei + EE;

    int *p_degi, *p_fill;
    __half *p_f16, *p_p1, *p_p2, *p_p3, *p_Whi;
    float *p_acc;
    cudaGetSymbolAddress((void**)&p_degi, g_degi);
    cudaGetSymbolAddress((void**)&p_fill, g_fill);
    cudaGetSymbolAddress((void**)&p_f16, g_f16);
    cudaGetSymbolAddress((void**)&p_p1, g_p1);
    cudaGetSymbolAddress((void**)&p_p2, g_p2);
    cudaGetSymbolAddress((void**)&p_p3, g_p3);
    cudaGetSymbolAddress((void**)&p_acc, g_acc);
    cudaGetSymbolAddress((void**)&p_Whi, g_Whi);

    const int SMEM_W = 2 * 128 * SLDA * 2;       // 69632 B
    const int SMEM_F = SMEM_W + 128 * SLDA * 4;  // 139264 B
    static bool attr_set = false;
    if (!attr_set) {
        cudaFuncSetAttribute(k_wgemm<0>, cudaFuncAttributeMaxDynamicSharedMemorySize, SMEM_W);
        cudaFuncSetAttribute(k_wgemm<2>, cudaFuncAttributeMaxDynamicSharedMemorySize, SMEM_W);
        cudaFuncSetAttribute(k_wgemm12, cudaFuncAttributeMaxDynamicSharedMemorySize, SMEM_W);
        cudaFuncSetAttribute(k_wfin, cudaFuncAttributeMaxDynamicSharedMemorySize, SMEM_F);
        attr_set = true;
    }

    const int egrid = (EE + 255) / 256;
    const int ngrid = (NN + 255) / 256;
    cudaStream_t s1 = R.s1;
    int evi = 0;

    // --- fork s1 FROM the captured origin stream (capture-legal) ---
    cudaEventRecord(R.ev[evi], 0);
    cudaStreamWaitEvent(s1, R.ev[evi], 0);
    evi++;

    // s1: conversions, then layer-1 gemm0
    k_cvt<<<SPMM_BLKS, 256, 0, s1>>>(x, W1, W2, W3, Wf);
    cudaEventRecord(R.ev[evi], s1);      // f16 ready (for s0's spmm1)
    int ev_cvt = evi++;
    k_wgemm<0><<<GEMM_BLKS, 256, SMEM_W, s1>>>(p_f16, p_Whi, p_acc,
                                               nullptr, nullptr);

    // s0: degree + scan + CSR fill (parallel to s1)
    k_zero2<<<ngrid, 256>>>(p_degi, p_fill);
    k_deg<<<egrid, 256>>>(col);
    k_blocksum<<<SCAN_BLKS, 256>>>();
    k_scanpart<<<1, 256>>>();
    k_scanfinal<<<SCAN_BLKS, 256>>>();
    k_fill<<<egrid, 256>>>(row, col);
    cudaStreamWaitEvent(0, R.ev[ev_cvt], 0);   // f16 ready before spmm1

    const float* bs[3] = {b1, b2, b3};

    for (int l = 0; l < 3; l++) {
        __half* Wl = p_Whi + (long)l * 4 * DD * DD;

        if (l > 0) {
            // gemm0 on s1 after prev epilogue (acc free, f16 fresh)
            cudaEventRecord(R.ev[evi], 0);
            cudaStreamWaitEvent(s1, R.ev[evi], 0);
            evi++;
            k_wgemm<0><<<GEMM_BLKS, 256, SMEM_W, s1>>>(p_f16, Wl, p_acc,
                                                       nullptr, nullptr);
        }

        k_spmm16<<<SPMM_BLKS, 256>>>(p_f16, p_p1);
        k_spmm16<<<SPMM_BLKS, 256>>>(p_p1, p_p2);
        cudaEventRecord(R.ev[evi], 0);
        cudaStreamWaitEvent(s1, R.ev[evi], 0);
        evi++;
        // acc += p1@W[1] + p2@W[2], hidden under spmm3
        k_wgemm12<<<GEMM_BLKS, 256, SMEM_W, s1>>>(p_p1, p_p2, Wl + DD * DD, p_acc);
        cudaEventRecord(R.ev[evi], s1);
        int ev_g12 = evi++;

        k_spmm16<<<SPMM_BLKS, 256>>>(p_p2, p_p3);
        cudaStreamWaitEvent(0, R.ev[ev_g12], 0);
        if (l < 2) {
            k_wgemm<2><<<GEMM_BLKS, 256, SMEM_W>>>(p_p3, Wl + 3 * DD * DD, p_acc,
                                                   bs[l], p_f16);
        } else {
            k_wfin<<<GEMM_BLKS, 256, SMEM_F>>>(p_p3, Wl + 3 * DD * DD, p_acc,
                                               b3, p_Whi + 12L * DD * DD, bf, out);
        }
    }
}

// round 14
// speedup vs baseline: 1.0793x; 1.0793x over previous
#include <cuda_runtime.h>
#include <cuda_fp16.h>
#include <mma.h>

using namespace nvcuda;

#define NN 50000
#define EE 1600000
#define DD 128
#define GEMM_BLKS 391           // ceil(50000/128)
#define SPMM_BLKS 6250          // ceil(50000/8)
#define SCAN_BLKS 196           // ceil(50000/256)
#define SLDA 136                // smem leading dim (halves / floats)

// ---------------- scratch (static device memory, allocation-free) ------------
__device__ __align__(16) int      g_degi[NN];
__device__ __align__(16) int      g_fill[NN];
__device__ __align__(16) int      g_rowptr[NN + 1];
__device__ __align__(16) float    g_dinv[NN];
__device__ __align__(16) int      g_part[256];
__device__ __align__(16) unsigned g_csrp[EE];       // low16 = src, high16 = fp16 weight
__device__ __align__(16) __half   g_f16[(long)NN * DD];
__device__ __align__(16) __half   g_p1[(long)NN * DD];
__device__ __align__(16) __half   g_p2[(long)NN * DD];
__device__ __align__(16) __half   g_p3[(long)NN * DD];
__device__ __align__(16) float    g_acc[(long)NN * DD];
__device__ __align__(16) __half   g_Whi[13 * DD * DD];

// ---------------- setup kernels -----------------------------------------------
__global__ void k_zero2(int* __restrict__ a, int* __restrict__ b) {
    int i = blockIdx.x * blockDim.x + threadIdx.x;
    if (i < NN) { a[i] = 0; b[i] = 0; }
}

// fused: x -> fp16 plane, weight fp16 convert, degree count (index-disjoint)
__global__ void k_cvtdeg(const float* __restrict__ x,
                         const float* __restrict__ W1, const float* __restrict__ W2,
                         const float* __restrict__ W3, const float* __restrict__ Wf,
                         const int* __restrict__ col) {
    long i = (long)blockIdx.x * blockDim.x + threadIdx.x;
    const long xtot = (long)NN * DD / 4;
    if (i < xtot) {
        float4 v = ((const float4*)x)[i];
        __half2 a = __floats2half2_rn(v.x, v.y);
        __half2 b = __floats2half2_rn(v.z, v.w);
        uint2 o;
        o.x = *(const unsigned*)&a;
        o.y = *(const unsigned*)&b;
        ((uint2*)g_f16)[i] = o;
    }
    if (i < 13 * DD * DD) {
        int m = (int)(i >> 14);
        int r = (int)(i & 16383);
        const float* src;
        if (m < 4)       src = W1 + m * 16384;
        else if (m < 8)  src = W2 + (m - 4) * 16384;
        else if (m < 12) src = W3 + (m - 8) * 16384;
        else             src = Wf;
        g_Whi[i] = __float2half_rn(src[r]);
    }
    if (i < EE) atomicAdd(&g_degi[col[i]], 1);
}

__global__ void k_blocksum() {
    __shared__ int wsum[8];
    int tid = threadIdx.x, lane = tid & 31, wid = tid >> 5;
    int idx = blockIdx.x * 256 + tid;
    int v = (idx < NN) ? g_degi[idx] : 0;
#pragma unroll
    for (int o = 16; o > 0; o >>= 1) v += __shfl_down_sync(0xffffffffu, v, o);
    if (lane == 0) wsum[wid] = v;
    __syncthreads();
    if (tid == 0) {
        int s = 0;
#pragma unroll
        for (int w = 0; w < 8; w++) s += wsum[w];
        g_part[blockIdx.x] = s;
    }
}

__global__ void k_scanpart() {
    __shared__ int wsum[8];
    int tid = threadIdx.x, lane = tid & 31, wid = tid >> 5;
    int v = (tid < SCAN_BLKS) ? g_part[tid] : 0;
    int incl = v;
#pragma unroll
    for (int o = 1; o < 32; o <<= 1) {
        int t = __shfl_up_sync(0xffffffffu, incl, o);
        if (lane >= o) incl += t;
    }
    if (lane == 31) wsum[wid] = incl;
    __syncthreads();
    if (wid == 0 && lane < 8) {
        int t = wsum[lane];
        int ti = t;
#pragma unroll
        for (int o = 1; o < 8; o <<= 1) {
            int u = __shfl_up_sync(0xffu, ti, o);
            if (lane >= o) ti += u;
        }
        wsum[lane] = ti - t;
    }
    __syncthreads();
    if (tid < SCAN_BLKS) g_part[tid] = wsum[wid] + incl - v;
}

__global__ void k_scanfinal() {
    __shared__ int wsum[8];
    int tid = threadIdx.x, lane = tid & 31, wid = tid >> 5;
    int idx = blockIdx.x * 256 + tid;
    int v = (idx < NN) ? g_degi[idx] : 0;
    int incl = v;
#pragma unroll
    for (int o = 1; o < 32; o <<= 1) {
        int t = __shfl_up_sync(0xffffffffu, incl, o);
        if (lane >= o) incl += t;
    }
    if (lane == 31) wsum[wid] = incl;
    __syncthreads();
    if (wid == 0 && lane < 8) {
        int t = wsum[lane];
        int ti = t;
#pragma unroll
        for (int o = 1; o < 8; o <<= 1) {
            int u = __shfl_up_sync(0xffu, ti, o);
            if (lane >= o) ti += u;
        }
        wsum[lane] = ti - t;
    }
    __syncthreads();
    int excl = g_part[blockIdx.x] + wsum[wid] + incl - v;
    if (idx < NN) {
        g_rowptr[idx] = excl;
        g_dinv[idx] = v > 0 ? rsqrtf((float)v) : 0.f;
    }
    if (blockIdx.x == SCAN_BLKS - 1 && tid == 255) g_rowptr[NN] = excl + v;
}

__global__ void k_fill(const int* __restrict__ row, const int* __restrict__ col) {
    int e = blockIdx.x * blockDim.x + threadIdx.x;
    if (e >= EE) return;
    int s = row[e], c = col[e];
    int p = atomicAdd(&g_fill[c], 1) + g_rowptr[c];
    float w = g_dinv[s] * g_dinv[c];
    g_csrp[p] = (unsigned)s |
                ((unsigned)__half_as_ushort(__float2half_rn(w)) << 16);
}

// ---------------- SpMM fp16 packed-CSR ---------------------------------------
__device__ __forceinline__ float csr_w(unsigned c) {
    return __half2float(__ushort_as_half((unsigned short)(c >> 16)));
}

__global__ void __launch_bounds__(256)
k_spmm16(const __half* __restrict__ cur, __half* __restrict__ outp) {
    int node = blockIdx.x * 8 + (threadIdx.x >> 5);
    if (node >= NN) return;
    int lane = threadIdx.x & 31;
    int s = __ldg(&g_rowptr[node]);
    int e = __ldg(&g_rowptr[node + 1]);

    float4 acc = make_float4(0.f, 0.f, 0.f, 0.f);
    int i = s;
    for (; i + 3 < e; i += 4) {
        unsigned c0 = __ldg(&g_csrp[i]);
        unsigned c1 = __ldg(&g_csrp[i + 1]);
        unsigned c2 = __ldg(&g_csrp[i + 2]);
        unsigned c3 = __ldg(&g_csrp[i + 3]);
        uint2 r0 = __ldg(((const uint2*)(cur + (long)(c0 & 0xFFFF) * DD)) + lane);
        uint2 r1 = __ldg(((const uint2*)(cur + (long)(c1 & 0xFFFF) * DD)) + lane);
        uint2 r2 = __ldg(((const uint2*)(cur + (long)(c2 & 0xFFFF) * DD)) + lane);
        uint2 r3 = __ldg(((const uint2*)(cur + (long)(c3 & 0xFFFF) * DD)) + lane);
        float w0 = csr_w(c0), w1 = csr_w(c1), w2 = csr_w(c2), w3 = csr_w(c3);
        float2 a0 = __half22float2(*(const __half2*)&r0.x);
        float2 b0 = __half22float2(*(const __half2*)&r0.y);
        float2 a1 = __half22float2(*(const __half2*)&r1.x);
        float2 b1 = __half22float2(*(const __half2*)&r1.y);
        float2 a2 = __half22float2(*(const __half2*)&r2.x);
        float2 b2 = __half22float2(*(const __half2*)&r2.y);
        float2 a3 = __half22float2(*(const __half2*)&r3.x);
        float2 b3 = __half22float2(*(const __half2*)&r3.y);
        acc.x += w0 * a0.x + w1 * a1.x + w2 * a2.x + w3 * a3.x;
        acc.y += w0 * a0.y + w1 * a1.y + w2 * a2.y + w3 * a3.y;
        acc.z += w0 * b0.x + w1 * b1.x + w2 * b2.x + w3 * b3.x;
        acc.w += w0 * b0.y + w1 * b1.y + w2 * b2.y + w3 * b3.y;
    }
    for (; i < e; i++) {
        unsigned c0 = __ldg(&g_csrp[i]);
        uint2 r0 = __ldg(((const uint2*)(cur + (long)(c0 & 0xFFFF) * DD)) + lane);
        float w0 = csr_w(c0);
        float2 a0 = __half22float2(*(const __half2*)&r0.x);
        float2 b0 = __half22float2(*(const __half2*)&r0.y);
        acc.x += w0 * a0.x;
        acc.y += w0 * a0.y;
        acc.z += w0 * b0.x;
        acc.w += w0 * b0.y;
    }
    __half2 oa = __floats2half2_rn(acc.x, acc.y);
    __half2 ob = __floats2half2_rn(acc.z, acc.w);
    uint2 o;
    o.x = *(const unsigned*)&oa;
    o.y = *(const unsigned*)&ob;
    ((uint2*)(outp + (long)node * DD))[lane] = o;
}

// ---------------- shared GEMM helpers ----------------------------------------
__device__ __forceinline__ void stage_AB(const __half* __restrict__ A,
                                         const __half* __restrict__ W,
                                         __half* As, __half* Bh, int m0, int tid) {
#pragma unroll
    for (int it = 0; it < 8; it++) {
        int idx = it * 256 + tid;
        int row = idx >> 4;
        int c8 = (idx & 15) << 3;
        uint4 v = make_uint4(0u, 0u, 0u, 0u);
        if (m0 + row < NN) v = *(const uint4*)(A + (long)(m0 + row) * DD + c8);
        *(uint4*)(As + row * SLDA + c8) = v;
        *(uint4*)(Bh + row * SLDA + c8) = *(const uint4*)(W + row * DD + c8);
    }
}

template <typename FragAcc>
__device__ __forceinline__ void mma_tile1(const __half* As, const __half* Bh,
                                          FragAcc acc[2][4], int rw, int cw) {
#pragma unroll
    for (int k = 0; k < 8; k++) {
        wmma::fragment<wmma::matrix_a, 16, 16, 16, __half, wmma::row_major> a[2];
        wmma::load_matrix_sync(a[0], As + (rw + 0) * SLDA + k * 16, SLDA);
        wmma::load_matrix_sync(a[1], As + (rw + 16) * SLDA + k * 16, SLDA);
#pragma unroll
        for (int j = 0; j < 4; j++) {
            wmma::fragment<wmma::matrix_b, 16, 16, 16, __half, wmma::row_major> bh;
            wmma::load_matrix_sync(bh, Bh + (k * 16) * SLDA + cw + j * 16, SLDA);
#pragma unroll
            for (int i = 0; i < 2; i++)
                wmma::mma_sync(acc[i][j], a[i], bh, acc[i][j]);
        }
    }
}

// ---------------- wmma GEMM: 128x128 tile, K=128, single fp16 W --------------
// MODE 0: C = A@W   MODE 1: C += A@W   MODE 2: f16 = relu(C + A@W + bias)
template <int MODE>
__global__ void __launch_bounds__(256)
k_wgemm(const __half* __restrict__ A, const __half* __restrict__ W,
        float* __restrict__ C, const float* __restrict__ bias,
        __half* __restrict__ dst16) {
    extern __shared__ __align__(16) char smem_raw[];
    __half* As = (__half*)smem_raw;
    __half* Bh = As + 128 * SLDA;
    float*  Cs = (float*)smem_raw;

    int tid = threadIdx.x;
    int wid = tid >> 5;
    int m0 = blockIdx.x * 128;

    stage_AB(A, W, As, Bh, m0, tid);
    __syncthreads();

    int rw = (wid >> 1) * 32;
    int cw = (wid & 1) * 64;

    wmma::fragment<wmma::accumulator, 16, 16, 16, float> acc[2][4];
#pragma unroll
    for (int i = 0; i < 2; i++)
#pragma unroll
        for (int j = 0; j < 4; j++) wmma::fill_fragment(acc[i][j], 0.f);

    mma_tile1(As, Bh, acc, rw, cw);
    __syncthreads();

#pragma unroll
    for (int i = 0; i < 2; i++)
#pragma unroll
        for (int j = 0; j < 4; j++)
            wmma::store_matrix_sync(Cs + (rw + i * 16) * SLDA + cw + j * 16,
                                    acc[i][j], SLDA, wmma::mem_row_major);
    __syncthreads();

#pragma unroll
    for (int it = 0; it < 16; it++) {
        int q = it * 256 + tid;
        int row = q >> 5;
        int c4 = (q & 31) << 2;
        int r = m0 + row;
        if (r >= NN) continue;
        const float* cp = Cs + row * SLDA + c4;
        float4 v = make_float4(cp[0], cp[1], cp[2], cp[3]);
        if (MODE == 0) {
            *(float4*)(C + (long)r * DD + c4) = v;
        } else if (MODE == 1) {
            float4 o = *(const float4*)(C + (long)r * DD + c4);
            v.x += o.x; v.y += o.y; v.z += o.z; v.w += o.w;
            *(float4*)(C + (long)r * DD + c4) = v;
        } else {
            float4 o = *(const float4*)(C + (long)r * DD + c4);
            float4 bb = *(const float4*)(bias + c4);
            v.x = fmaxf(v.x + o.x + bb.x, 0.f);
            v.y = fmaxf(v.y + o.y + bb.y, 0.f);
            v.z = fmaxf(v.z + o.z + bb.z, 0.f);
            v.w = fmaxf(v.w + o.w + bb.w, 0.f);
            __half2 ha = __floats2half2_rn(v.x, v.y);
            __half2 hb = __floats2half2_rn(v.z, v.w);
            uint2 u;
            u.x = *(const unsigned*)&ha;
            u.y = *(const unsigned*)&hb;
            *(uint2*)(dst16 + (long)r * DD + c4) = u;
        }
    }
}

// ---------------- fused layer-3 epilogue + final GEMM ------------------------
// t = relu(acc + p3@W3 + b3) ; out = t @ Wf + bf
__global__ void __launch_bounds__(256)
k_wfin(const __half* __restrict__ p3, const __half* __restrict__ W3,
       const float* __restrict__ accg, const float* __restrict__ b3,
       const __half* __restrict__ Wf, const float* __restrict__ bf,
       float* __restrict__ outp) {
    extern __shared__ __align__(16) char smem_raw[];
    __half* As = (__half*)smem_raw;                       // region0 A tile
    __half* Bh = As + 128 * SLDA;                         // region0 B tile
    float*  Cs = (float*)(smem_raw + 2 * 128 * SLDA * 2); // region1

    int tid = threadIdx.x;
    int wid = tid >> 5;
    int m0 = blockIdx.x * 128;
    int rw = (wid >> 1) * 32;
    int cw = (wid & 1) * 64;

    wmma::fragment<wmma::accumulator, 16, 16, 16, float> acc[2][4];

    // --- stage 1: p3 @ W3 ---
    stage_AB(p3, W3, As, Bh, m0, tid);
    __syncthreads();
#pragma unroll
    for (int i = 0; i < 2; i++)
#pragma unroll
        for (int j = 0; j < 4; j++) wmma::fill_fragment(acc[i][j], 0.f);
    mma_tile1(As, Bh, acc, rw, cw);
#pragma unroll
    for (int i = 0; i < 2; i++)
#pragma unroll
        for (int j = 0; j < 4; j++)
            wmma::store_matrix_sync(Cs + (rw + i * 16) * SLDA + cw + j * 16,
                                    acc[i][j], SLDA, wmma::mem_row_major);
    __syncthreads();   // MMA1 + Cs stores done; As/Bh free for reuse

    // --- epilogue to fp16 tile in As ---
#pragma unroll
    for (int it = 0; it < 16; it++) {
        int q = it * 256 + tid;
        int row = q >> 5;
        int c4 = (q & 31) << 2;
        int r = m0 + row;
        float4 v = make_float4(0.f, 0.f, 0.f, 0.f);
        if (r < NN) {
            const float* cp = Cs + row * SLDA + c4;
            float4 o = *(const float4*)(accg + (long)r * DD + c4);
            float4 bb = *(const float4*)(b3 + c4);
            v.x = fmaxf(cp[0] + o.x + bb.x, 0.f);
            v.y = fmaxf(cp[1] + o.y + bb.y, 0.f);
            v.z = fmaxf(cp[2] + o.z + bb.z, 0.f);
            v.w = fmaxf(cp[3] + o.w + bb.w, 0.f);
        }
        __half2 ha = __floats2half2_rn(v.x, v.y);
        __half2 hb = __floats2half2_rn(v.z, v.w);
        uint2 u;
        u.x = *(const unsigned*)&ha;
        u.y = *(const unsigned*)&hb;
        *(uint2*)(As + row * SLDA + c4) = u;
    }
    // stage Wf into Bh
#pragma unroll
    for (int it = 0; it < 8; it++) {
        int idx = it * 256 + tid;
        int row = idx >> 4;
        int c8 = (idx & 15) << 3;
        *(uint4*)(Bh + row * SLDA + c8) = *(const uint4*)(Wf + row * DD + c8);
    }
    __syncthreads();

    // --- stage 2: t @ Wf ---
#pragma unroll
    for (int i = 0; i < 2; i++)
#pragma unroll
        for (int j = 0; j < 4; j++) wmma::fill_fragment(acc[i][j], 0.f);
    mma_tile1(As, Bh, acc, rw, cw);
#pragma unroll
    for (int i = 0; i < 2; i++)
#pragma unroll
        for (int j = 0; j < 4; j++)
            wmma::store_matrix_sync(Cs + (rw + i * 16) * SLDA + cw + j * 16,
                                    acc[i][j], SLDA, wmma::mem_row_major);
    __syncthreads();

#pragma unroll
    for (int it = 0; it < 16; it++) {
        int q = it * 256 + tid;
        int row = q >> 5;
        int c4 = (q & 31) << 2;
        int r = m0 + row;
        if (r >= NN) continue;
        const float* cp = Cs + row * SLDA + c4;
        float4 bb = *(const float4*)(bf + c4);
        float4 v = make_float4(cp[0] + bb.x, cp[1] + bb.y,
                               cp[2] + bb.z, cp[3] + bb.w);
        *(float4*)(outp + (long)r * DD + c4) = v;
    }
}

// ---------------- stream/event resources (built once, outside capture) -------
struct OverlapRes {
    cudaStream_t s1;
    cudaEvent_t ev[16];
    OverlapRes() {
        cudaStreamCreateWithFlags(&s1, cudaStreamNonBlocking);
        for (int i = 0; i < 16; i++)
            cudaEventCreateWithFlags(&ev[i], cudaEventDisableTiming);
    }
};

// ---------------- host orchestration -----------------------------------------
extern "C" void kernel_launch(void* const* d_in, const int* in_sizes, int n_in,
                              void* d_out, int out_size) {
    static OverlapRes R;  // created on first (uncaptured) correctness call

    const float* x  = (const float*)d_in[0];
    const int*   ei = (const int*)d_in[1];
    const float* W1 = (const float*)d_in[2];
    const float* b1 = (const float*)d_in[3];
    const float* W2 = (const float*)d_in[4];
    const float* b2 = (const float*)d_in[5];
    const float* W3 = (const float*)d_in[6];
    const float* b3 = (const float*)d_in[7];
    const float* Wf = (const float*)d_in[8];
    const float* bf = (const float*)d_in[9];
    float* out = (float*)d_out;

    const int* row = ei;
    const int* col = ei + EE;

    int *p_degi, *p_fill;
    __half *p_f16, *p_p1, *p_p2, *p_p3, *p_Whi;
    float *p_acc;
    cudaGetSymbolAddress((void**)&p_degi, g_degi);
    cudaGetSymbolAddress((void**)&p_fill, g_fill);
    cudaGetSymbolAddress((void**)&p_f16, g_f16);
    cudaGetSymbolAddress((void**)&p_p1, g_p1);
    cudaGetSymbolAddress((void**)&p_p2, g_p2);
    cudaGetSymbolAddress((void**)&p_p3, g_p3);
    cudaGetSymbolAddress((void**)&p_acc, g_acc);
    cudaGetSymbolAddress((void**)&p_Whi, g_Whi);

    const int SMEM_W = 2 * 128 * SLDA * 2;       // 69632 B
    const int SMEM_F = SMEM_W + 128 * SLDA * 4;  // 139264 B
    static bool attr_set = false;
    if (!attr_set) {
        cudaFuncSetAttribute(k_wgemm<0>, cudaFuncAttributeMaxDynamicSharedMemorySize, SMEM_W);
        cudaFuncSetAttribute(k_wgemm<1>, cudaFuncAttributeMaxDynamicSharedMemorySize, SMEM_W);
        cudaFuncSetAttribute(k_wgemm<2>, cudaFuncAttributeMaxDynamicSharedMemorySize, SMEM_W);
        cudaFuncSetAttribute(k_wfin, cudaFuncAttributeMaxDynamicSharedMemorySize, SMEM_F);
        attr_set = true;
    }

    const int egrid = (EE + 255) / 256;
    const int ngrid = (NN + 255) / 256;
    cudaStream_t s1 = R.s1;
    int evi = 0;

    // --- s0: zero, then fused convert + degree ---
    k_zero2<<<ngrid, 256>>>(p_degi, p_fill);
    k_cvtdeg<<<SPMM_BLKS, 256>>>(x, W1, W2, W3, Wf, col);

    // Fork s1: layer-1 gemm0 (x16 @ W1[0]) after conversions.
    cudaEventRecord(R.ev[evi], 0);
    cudaStreamWaitEvent(s1, R.ev[evi], 0);
    evi++;
    k_wgemm<0><<<GEMM_BLKS, 256, SMEM_W, s1>>>(p_f16, p_Whi, p_acc,
                                               nullptr, nullptr);

    // --- s0: scan + CSR fill ---
    k_blocksum<<<SCAN_BLKS, 256>>>();
    k_scanpart<<<1, 256>>>();
    k_scanfinal<<<SCAN_BLKS, 256>>>();
    k_fill<<<egrid, 256>>>(row, col);

    const float* bs[3] = {b1, b2, b3};

    for (int l = 0; l < 3; l++) {
        __half* Wl = p_Whi + (long)l * 4 * DD * DD;

        if (l > 0) {
            cudaEventRecord(R.ev[evi], 0);
            cudaStreamWaitEvent(s1, R.ev[evi], 0);
            evi++;
            k_wgemm<0><<<GEMM_BLKS, 256, SMEM_W, s1>>>(p_f16, Wl, p_acc,
                                                       nullptr, nullptr);
        }

        k_spmm16<<<SPMM_BLKS, 256>>>(p_f16, p_p1);
        cudaEventRecord(R.ev[evi], 0);
        cudaStreamWaitEvent(s1, R.ev[evi], 0);
        evi++;
        k_wgemm<1><<<GEMM_BLKS, 256, SMEM_W, s1>>>(p_p1, Wl + DD * DD, p_acc,
                                                   nullptr, nullptr);

        k_spmm16<<<SPMM_BLKS, 256>>>(p_p1, p_p2);
        cudaEventRecord(R.ev[evi], 0);
        cudaStreamWaitEvent(s1, R.ev[evi], 0);
        k_wgemm<1><<<GEMM_BLKS, 256, SMEM_W, s1>>>(p_p2, Wl + 2 * DD * DD, p_acc,
                                                   nullptr, nullptr);
        cudaEventRecord(R.ev[evi + 1], s1);

        k_spmm16<<<SPMM_BLKS, 256>>>(p_p2, p_p3);
        cudaStreamWaitEvent(0, R.ev[evi + 1], 0);
        evi += 2;
        if (l < 2) {
            k_wgemm<2><<<GEMM_BLKS, 256, SMEM_W>>>(p_p3, Wl + 3 * DD * DD, p_acc,
                                                   bs[l], p_f16);
        } else {
            k_wfin<<<GEMM_BLKS, 256, SMEM_F>>>(p_p3, Wl + 3 * DD * DD, p_acc,
                                               b3, p_Whi + 12L * DD * DD, bf, out);
        }
    }
}

// round 15
// speedup vs baseline: 1.1405x; 1.0567x over previous
#include <cuda_runtime.h>
#include <cuda_fp16.h>
#include <mma.h>

using namespace nvcuda;

#define NN 50000
#define EE 1600000
#define DD 128
#define GEMM_BLKS 391           // ceil(50000/128)
#define SPMM_BLKS 3125          // ceil(50000/16): 16 nodes per 256-thr block
#define SCAN_BLKS 196           // ceil(50000/256)
#define SLDA 136                // smem leading dim (halves / floats)

// ---------------- scratch (static device memory, allocation-free) ------------
__device__ __align__(16) int      g_degi[NN];
__device__ __align__(16) int      g_fill[NN];
__device__ __align__(16) int      g_rowptr[NN + 1];
__device__ __align__(16) float    g_dinv[NN];
__device__ __align__(16) int      g_part[256];
__device__ __align__(16) unsigned g_csrp[EE];       // low16 = src, high16 = fp16 weight
__device__ __align__(16) __half   g_f16[(long)NN * DD];
__device__ __align__(16) __half   g_p1[(long)NN * DD];
__device__ __align__(16) __half   g_p2[(long)NN * DD];
__device__ __align__(16) __half   g_p3[(long)NN * DD];
__device__ __align__(16) float    g_acc[(long)NN * DD];
__device__ __align__(16) __half   g_Whi[13 * DD * DD];

// ---------------- setup kernels -----------------------------------------------
__global__ void k_zero2(int* __restrict__ a, int* __restrict__ b) {
    int i = blockIdx.x * blockDim.x + threadIdx.x;
    if (i < NN) { a[i] = 0; b[i] = 0; }
}

// fused: x -> fp16 plane, weight fp16 convert, degree count (index-disjoint)
__global__ void k_cvtdeg(const float* __restrict__ x,
                         const float* __restrict__ W1, const float* __restrict__ W2,
                         const float* __restrict__ W3, const float* __restrict__ Wf,
                         const int* __restrict__ col) {
    long i = (long)blockIdx.x * blockDim.x + threadIdx.x;
    const long xtot = (long)NN * DD / 4;
    if (i < xtot) {
        float4 v = ((const float4*)x)[i];
        __half2 a = __floats2half2_rn(v.x, v.y);
        __half2 b = __floats2half2_rn(v.z, v.w);
        uint2 o;
        o.x = *(const unsigned*)&a;
        o.y = *(const unsigned*)&b;
        ((uint2*)g_f16)[i] = o;
    }
    if (i < 13 * DD * DD) {
        int m = (int)(i >> 14);
        int r = (int)(i & 16383);
        const float* src;
        if (m < 4)       src = W1 + m * 16384;
        else if (m < 8)  src = W2 + (m - 4) * 16384;
        else if (m < 12) src = W3 + (m - 8) * 16384;
        else             src = Wf;
        g_Whi[i] = __float2half_rn(src[r]);
    }
    if (i < EE) atomicAdd(&g_degi[col[i]], 1);
}

__global__ void k_blocksum() {
    __shared__ int wsum[8];
    int tid = threadIdx.x, lane = tid & 31, wid = tid >> 5;
    int idx = blockIdx.x * 256 + tid;
    int v = (idx < NN) ? g_degi[idx] : 0;
#pragma unroll
    for (int o = 16; o > 0; o >>= 1) v += __shfl_down_sync(0xffffffffu, v, o);
    if (lane == 0) wsum[wid] = v;
    __syncthreads();
    if (tid == 0) {
        int s = 0;
#pragma unroll
        for (int w = 0; w < 8; w++) s += wsum[w];
        g_part[blockIdx.x] = s;
    }
}

__global__ void k_scanpart() {
    __shared__ int wsum[8];
    int tid = threadIdx.x, lane = tid & 31, wid = tid >> 5;
    int v = (tid < SCAN_BLKS) ? g_part[tid] : 0;
    int incl = v;
#pragma unroll
    for (int o = 1; o < 32; o <<= 1) {
        int t = __shfl_up_sync(0xffffffffu, incl, o);
        if (lane >= o) incl += t;
    }
    if (lane == 31) wsum[wid] = incl;
    __syncthreads();
    if (wid == 0 && lane < 8) {
        int t = wsum[lane];
        int ti = t;
#pragma unroll
        for (int o = 1; o < 8; o <<= 1) {
            int u = __shfl_up_sync(0xffu, ti, o);
            if (lane >= o) ti += u;
        }
        wsum[lane] = ti - t;
    }
    __syncthreads();
    if (tid < SCAN_BLKS) g_part[tid] = wsum[wid] + incl - v;
}

__global__ void k_scanfinal() {
    __shared__ int wsum[8];
    int tid = threadIdx.x, lane = tid & 31, wid = tid >> 5;
    int idx = blockIdx.x * 256 + tid;
    int v = (idx < NN) ? g_degi[idx] : 0;
    int incl = v;
#pragma unroll
    for (int o = 1; o < 32; o <<= 1) {
        int t = __shfl_up_sync(0xffffffffu, incl, o);
        if (lane >= o) incl += t;
    }
    if (lane == 31) wsum[wid] = incl;
    __syncthreads();
    if (wid == 0 && lane < 8) {
        int t = wsum[lane];
        int ti = t;
#pragma unroll
        for (int o = 1; o < 8; o <<= 1) {
            int u = __shfl_up_sync(0xffu, ti, o);
            if (lane >= o) ti += u;
        }
        wsum[lane] = ti - t;
    }
    __syncthreads();
    int excl = g_part[blockIdx.x] + wsum[wid] + incl - v;
    if (idx < NN) {
        g_rowptr[idx] = excl;
        g_dinv[idx] = v > 0 ? rsqrtf((float)v) : 0.f;
    }
    if (blockIdx.x == SCAN_BLKS - 1 && tid == 255) g_rowptr[NN] = excl + v;
}

__global__ void k_fill(const int* __restrict__ row, const int* __restrict__ col) {
    int e = blockIdx.x * blockDim.x + threadIdx.x;
    if (e >= EE) return;
    int s = row[e], c = col[e];
    int p = atomicAdd(&g_fill[c], 1) + g_rowptr[c];
    float w = g_dinv[s] * g_dinv[c];
    g_csrp[p] = (unsigned)s |
                ((unsigned)__half_as_ushort(__float2half_rn(w)) << 16);
}

// ---------------- SpMM fp16 packed-CSR: 2 nodes/warp, uint4 loads ------------
__device__ __forceinline__ float csr_w(unsigned c) {
    return __half2float(__ushort_as_half((unsigned short)(c >> 16)));
}

__device__ __forceinline__ void fma8(float* acc, uint4 r, float w) {
    float2 t;
    t = __half22float2(*(const __half2*)&r.x); acc[0] += w * t.x; acc[1] += w * t.y;
    t = __half22float2(*(const __half2*)&r.y); acc[2] += w * t.x; acc[3] += w * t.y;
    t = __half22float2(*(const __half2*)&r.z); acc[4] += w * t.x; acc[5] += w * t.y;
    t = __half22float2(*(const __half2*)&r.w); acc[6] += w * t.x; acc[7] += w * t.y;
}

__global__ void __launch_bounds__(256)
k_spmm16(const __half* __restrict__ cur, __half* __restrict__ outp) {
    int node = blockIdx.x * 16 + (threadIdx.x >> 4);   // 16 lanes per node
    if (node >= NN) return;
    int lane = threadIdx.x & 15;                       // lane owns 8 halves
    int s = __ldg(&g_rowptr[node]);
    int e = __ldg(&g_rowptr[node + 1]);

    float acc[8];
#pragma unroll
    for (int k = 0; k < 8; k++) acc[k] = 0.f;

    int i = s;
    for (; i + 3 < e; i += 4) {
        unsigned c0 = __ldg(&g_csrp[i]);
        unsigned c1 = __ldg(&g_csrp[i + 1]);
        unsigned c2 = __ldg(&g_csrp[i + 2]);
        unsigned c3 = __ldg(&g_csrp[i + 3]);
        uint4 r0 = __ldg(((const uint4*)(cur + (long)(c0 & 0xFFFF) * DD)) + lane);
        uint4 r1 = __ldg(((const uint4*)(cur + (long)(c1 & 0xFFFF) * DD)) + lane);
        uint4 r2 = __ldg(((const uint4*)(cur + (long)(c2 & 0xFFFF) * DD)) + lane);
        uint4 r3 = __ldg(((const uint4*)(cur + (long)(c3 & 0xFFFF) * DD)) + lane);
        fma8(acc, r0, csr_w(c0));
        fma8(acc, r1, csr_w(c1));
        fma8(acc, r2, csr_w(c2));
        fma8(acc, r3, csr_w(c3));
    }
    for (; i < e; i++) {
        unsigned c0 = __ldg(&g_csrp[i]);
        uint4 r0 = __ldg(((const uint4*)(cur + (long)(c0 & 0xFFFF) * DD)) + lane);
        fma8(acc, r0, csr_w(c0));
    }

    uint4 o;
    __half2 h01 = __floats2half2_rn(acc[0], acc[1]);
    __half2 h23 = __floats2half2_rn(acc[2], acc[3]);
    __half2 h45 = __floats2half2_rn(acc[4], acc[5]);
    __half2 h67 = __floats2half2_rn(acc[6], acc[7]);
    o.x = *(const unsigned*)&h01;
    o.y = *(const unsigned*)&h23;
    o.z = *(const unsigned*)&h45;
    o.w = *(const unsigned*)&h67;
    ((uint4*)(outp + (long)node * DD))[lane] = o;
}

// ---------------- shared GEMM helpers ----------------------------------------
__device__ __forceinline__ void stage_AB(const __half* __restrict__ A,
                                         const __half* __restrict__ W,
                                         __half* As, __half* Bh, int m0, int tid) {
#pragma unroll
    for (int it = 0; it < 8; it++) {
        int idx = it * 256 + tid;
        int row = idx >> 4;
        int c8 = (idx & 15) << 3;
        uint4 v = make_uint4(0u, 0u, 0u, 0u);
        if (m0 + row < NN) v = *(const uint4*)(A + (long)(m0 + row) * DD + c8);
        *(uint4*)(As + row * SLDA + c8) = v;
        *(uint4*)(Bh + row * SLDA + c8) = *(const uint4*)(W + row * DD + c8);
    }
}

template <typename FragAcc>
__device__ __forceinline__ void mma_tile1(const __half* As, const __half* Bh,
                                          FragAcc acc[2][4], int rw, int cw) {
#pragma unroll
    for (int k = 0; k < 8; k++) {
        wmma::fragment<wmma::matrix_a, 16, 16, 16, __half, wmma::row_major> a[2];
        wmma::load_matrix_sync(a[0], As + (rw + 0) * SLDA + k * 16, SLDA);
        wmma::load_matrix_sync(a[1], As + (rw + 16) * SLDA + k * 16, SLDA);
#pragma unroll
        for (int j = 0; j < 4; j++) {
            wmma::fragment<wmma::matrix_b, 16, 16, 16, __half, wmma::row_major> bh;
            wmma::load_matrix_sync(bh, Bh + (k * 16) * SLDA + cw + j * 16, SLDA);
#pragma unroll
            for (int i = 0; i < 2; i++)
                wmma::mma_sync(acc[i][j], a[i], bh, acc[i][j]);
        }
    }
}

// ---------------- wmma GEMM: 128x128 tile, K=128, single fp16 W --------------
// MODE 0: C = A@W   MODE 1: C += A@W   MODE 2: f16 = relu(C + A@W + bias)
template <int MODE>
__global__ void __launch_bounds__(256)
k_wgemm(const __half* __restrict__ A, const __half* __restrict__ W,
        float* __restrict__ C, const float* __restrict__ bias,
        __half* __restrict__ dst16) {
    extern __shared__ __align__(16) char smem_raw[];
    __half* As = (__half*)smem_raw;
    __half* Bh = As + 128 * SLDA;
    float*  Cs = (float*)smem_raw;

    int tid = threadIdx.x;
    int wid = tid >> 5;
    int m0 = blockIdx.x * 128;

    stage_AB(A, W, As, Bh, m0, tid);
    __syncthreads();

    int rw = (wid >> 1) * 32;
    int cw = (wid & 1) * 64;

    wmma::fragment<wmma::accumulator, 16, 16, 16, float> acc[2][4];
#pragma unroll
    for (int i = 0; i < 2; i++)
#pragma unroll
        for (int j = 0; j < 4; j++) wmma::fill_fragment(acc[i][j], 0.f);

    mma_tile1(As, Bh, acc, rw, cw);
    __syncthreads();

#pragma unroll
    for (int i = 0; i < 2; i++)
#pragma unroll
        for (int j = 0; j < 4; j++)
            wmma::store_matrix_sync(Cs + (rw + i * 16) * SLDA + cw + j * 16,
                                    acc[i][j], SLDA, wmma::mem_row_major);
    __syncthreads();

#pragma unroll
    for (int it = 0; it < 16; it++) {
        int q = it * 256 + tid;
        int row = q >> 5;
        int c4 = (q & 31) << 2;
        int r = m0 + row;
        if (r >= NN) continue;
        const float* cp = Cs + row * SLDA + c4;
        float4 v = make_float4(cp[0], cp[1], cp[2], cp[3]);
        if (MODE == 0) {
            *(float4*)(C + (long)r * DD + c4) = v;
        } else if (MODE == 1) {
            float4 o = *(const float4*)(C + (long)r * DD + c4);
            v.x += o.x; v.y += o.y; v.z += o.z; v.w += o.w;
            *(float4*)(C + (long)r * DD + c4) = v;
        } else {
            float4 o = *(const float4*)(C + (long)r * DD + c4);
            float4 bb = *(const float4*)(bias + c4);
            v.x = fmaxf(v.x + o.x + bb.x, 0.f);
            v.y = fmaxf(v.y + o.y + bb.y, 0.f);
            v.z = fmaxf(v.z + o.z + bb.z, 0.f);
            v.w = fmaxf(v.w + o.w + bb.w, 0.f);
            __half2 ha = __floats2half2_rn(v.x, v.y);
            __half2 hb = __floats2half2_rn(v.z, v.w);
            uint2 u;
            u.x = *(const unsigned*)&ha;
            u.y = *(const unsigned*)&hb;
            *(uint2*)(dst16 + (long)r * DD + c4) = u;
        }
    }
}

// ---------------- fused layer-3 epilogue + final GEMM ------------------------
// t = relu(acc + p3@W3 + b3) ; out = t @ Wf + bf
__global__ void __launch_bounds__(256)
k_wfin(const __half* __restrict__ p3, const __half* __restrict__ W3,
       const float* __restrict__ accg, const float* __restrict__ b3,
       const __half* __restrict__ Wf, const float* __restrict__ bf,
       float* __restrict__ outp) {
    extern __shared__ __align__(16) char smem_raw[];
    __half* As = (__half*)smem_raw;                       // region0 A tile
    __half* Bh = As + 128 * SLDA;                         // region0 B tile
    float*  Cs = (float*)(smem_raw + 2 * 128 * SLDA * 2); // region1

    int tid = threadIdx.x;
    int wid = tid >> 5;
    int m0 = blockIdx.x * 128;
    int rw = (wid >> 1) * 32;
    int cw = (wid & 1) * 64;

    wmma::fragment<wmma::accumulator, 16, 16, 16, float> acc[2][4];

    // --- stage 1: p3 @ W3 ---
    stage_AB(p3, W3, As, Bh, m0, tid);
    __syncthreads();
#pragma unroll
    for (int i = 0; i < 2; i++)
#pragma unroll
        for (int j = 0; j < 4; j++) wmma::fill_fragment(acc[i][j], 0.f);
    mma_tile1(As, Bh, acc, rw, cw);
#pragma unroll
    for (int i = 0; i < 2; i++)
#pragma unroll
        for (int j = 0; j < 4; j++)
            wmma::store_matrix_sync(Cs + (rw + i * 16) * SLDA + cw + j * 16,
                                    acc[i][j], SLDA, wmma::mem_row_major);
    __syncthreads();   // MMA1 + Cs stores done; As/Bh free for reuse

    // --- epilogue to fp16 tile in As ---
#pragma unroll
    for (int it = 0; it < 16; it++) {
        int q = it * 256 + tid;
        int row = q >> 5;
        int c4 = (q & 31) << 2;
        int r = m0 + row;
        float4 v = make_float4(0.f, 0.f, 0.f, 0.f);
        if (r < NN) {
            const float* cp = Cs + row * SLDA + c4;
            float4 o = *(const float4*)(accg + (long)r * DD + c4);
            float4 bb = *(const float4*)(b3 + c4);
            v.x = fmaxf(cp[0] + o.x + bb.x, 0.f);
            v.y = fmaxf(cp[1] + o.y + bb.y, 0.f);
            v.z = fmaxf(cp[2] + o.z + bb.z, 0.f);
            v.w = fmaxf(cp[3] + o.w + bb.w, 0.f);
        }
        __half2 ha = __floats2half2_rn(v.x, v.y);
        __half2 hb = __floats2half2_rn(v.z, v.w);
        uint2 u;
        u.x = *(const unsigned*)&ha;
        u.y = *(const unsigned*)&hb;
        *(uint2*)(As + row * SLDA + c4) = u;
    }
    // stage Wf into Bh
#pragma unroll
    for (int it = 0; it < 8; it++) {
        int idx = it * 256 + tid;
        int row = idx >> 4;
        int c8 = (idx & 15) << 3;
        *(uint4*)(Bh + row * SLDA + c8) = *(const uint4*)(Wf + row * DD + c8);
    }
    __syncthreads();

    // --- stage 2: t @ Wf ---
#pragma unroll
    for (int i = 0; i < 2; i++)
#pragma unroll
        for (int j = 0; j < 4; j++) wmma::fill_fragment(acc[i][j], 0.f);
    mma_tile1(As, Bh, acc, rw, cw);
#pragma unroll
    for (int i = 0; i < 2; i++)
#pragma unroll
        for (int j = 0; j < 4; j++)
            wmma::store_matrix_sync(Cs + (rw + i * 16) * SLDA + cw + j * 16,
                                    acc[i][j], SLDA, wmma::mem_row_major);
    __syncthreads();

#pragma unroll
    for (int it = 0; it < 16; it++) {
        int q = it * 256 + tid;
        int row = q >> 5;
        int c4 = (q & 31) << 2;
        int r = m0 + row;
        if (r >= NN) continue;
        const float* cp = Cs + row * SLDA + c4;
        float4 bb = *(const float4*)(bf + c4);
        float4 v = make_float4(cp[0] + bb.x, cp[1] + bb.y,
                               cp[2] + bb.z, cp[3] + bb.w);
        *(float4*)(outp + (long)r * DD + c4) = v;
    }
}

// ---------------- stream/event resources (built once, outside capture) -------
struct OverlapRes {
    cudaStream_t s1;
    cudaEvent_t ev[16];
    OverlapRes() {
        cudaStreamCreateWithFlags(&s1, cudaStreamNonBlocking);
        for (int i = 0; i < 16; i++)
            cudaEventCreateWithFlags(&ev[i], cudaEventDisableTiming);
    }
};

// ---------------- host orchestration -----------------------------------------
extern "C" void kernel_launch(void* const* d_in, const int* in_sizes, int n_in,
                              void* d_out, int out_size) {
    static OverlapRes R;  // created on first (uncaptured) correctness call

    const float* x  = (const float*)d_in[0];
    const int*   ei = (const int*)d_in[1];
    const float* W1 = (const float*)d_in[2];
    const float* b1 = (const float*)d_in[3];
    const float* W2 = (const float*)d_in[4];
    const float* b2 = (const float*)d_in[5];
    const float* W3 = (const float*)d_in[6];
    const float* b3 = (const float*)d_in[7];
    const float* Wf = (const float*)d_in[8];
    const float* bf = (const float*)d_in[9];
    float* out = (float*)d_out;

    const int* row = ei;
    const int* col = ei + EE;

    int *p_degi, *p_fill;
    __half *p_f16, *p_p1, *p_p2, *p_p3, *p_Whi;
    float *p_acc;
    cudaGetSymbolAddress((void**)&p_degi, g_degi);
    cudaGetSymbolAddress((void**)&p_fill, g_fill);
    cudaGetSymbolAddress((void**)&p_f16, g_f16);
    cudaGetSymbolAddress((void**)&p_p1, g_p1);
    cudaGetSymbolAddress((void**)&p_p2, g_p2);
    cudaGetSymbolAddress((void**)&p_p3, g_p3);
    cudaGetSymbolAddress((void**)&p_acc, g_acc);
    cudaGetSymbolAddress((void**)&p_Whi, g_Whi);

    const int SMEM_W = 2 * 128 * SLDA * 2;       // 69632 B
    const int SMEM_F = SMEM_W + 128 * SLDA * 4;  // 139264 B
    static bool attr_set = false;
    if (!attr_set) {
        cudaFuncSetAttribute(k_wgemm<0>, cudaFuncAttributeMaxDynamicSharedMemorySize, SMEM_W);
        cudaFuncSetAttribute(k_wgemm<1>, cudaFuncAttributeMaxDynamicSharedMemorySize, SMEM_W);
        cudaFuncSetAttribute(k_wgemm<2>, cudaFuncAttributeMaxDynamicSharedMemorySize, SMEM_W);
        cudaFuncSetAttribute(k_wfin, cudaFuncAttributeMaxDynamicSharedMemorySize, SMEM_F);
        attr_set = true;
    }

    const int egrid = (EE + 255) / 256;
    const int ngrid = (NN + 255) / 256;
    const int cvtgrid = 6250;   // covers max(xtot, EE/256) indices
    cudaStream_t s1 = R.s1;
    int evi = 0;

    // --- s0: zero, then fused convert + degree ---
    k_zero2<<<ngrid, 256>>>(p_degi, p_fill);
    k_cvtdeg<<<cvtgrid, 256>>>(x, W1, W2, W3, Wf, col);

    // Fork s1: layer-1 gemm0 (x16 @ W1[0]) after conversions.
    cudaEventRecord(R.ev[evi], 0);
    cudaStreamWaitEvent(s1, R.ev[evi], 0);
    evi++;
    k_wgemm<0><<<GEMM_BLKS, 256, SMEM_W, s1>>>(p_f16, p_Whi, p_acc,
                                               nullptr, nullptr);

    // --- s0: scan + CSR fill ---
    k_blocksum<<<SCAN_BLKS, 256>>>();
    k_scanpart<<<1, 256>>>();
    k_scanfinal<<<SCAN_BLKS, 256>>>();
    k_fill<<<egrid, 256>>>(row, col);

    const float* bs[3] = {b1, b2, b3};

    for (int l = 0; l < 3; l++) {
        __half* Wl = p_Whi + (long)l * 4 * DD * DD;

        if (l > 0) {
            cudaEventRecord(R.ev[evi], 0);
            cudaStreamWaitEvent(s1, R.ev[evi], 0);
            evi++;
            k_wgemm<0><<<GEMM_BLKS, 256, SMEM_W, s1>>>(p_f16, Wl, p_acc,
                                                       nullptr, nullptr);
        }

        k_spmm16<<<SPMM_BLKS, 256>>>(p_f16, p_p1);
        cudaEventRecord(R.ev[evi], 0);
        cudaStreamWaitEvent(s1, R.ev[evi], 0);
        evi++;
        k_wgemm<1><<<GEMM_BLKS, 256, SMEM_W, s1>>>(p_p1, Wl + DD * DD, p_acc,
                                                   nullptr, nullptr);

        k_spmm16<<<SPMM_BLKS, 256>>>(p_p1, p_p2);
        cudaEventRecord(R.ev[evi], 0);
        cudaStreamWaitEvent(s1, R.ev[evi], 0);
        k_wgemm<1><<<GEMM_BLKS, 256, SMEM_W, s1>>>(p_p2, Wl + 2 * DD * DD, p_acc,
                                                   nullptr, nullptr);
        cudaEventRecord(R.ev[evi + 1], s1);

        k_spmm16<<<SPMM_BLKS, 256>>>(p_p2, p_p3);
        cudaStreamWaitEvent(0, R.ev[evi + 1], 0);
        evi += 2;
        if (l < 2) {
            k_wgemm<2><<<GEMM_BLKS, 256, SMEM_W>>>(p_p3, Wl + 3 * DD * DD, p_acc,
                                                   bs[l], p_f16);
        } else {
            k_wfin<<<GEMM_BLKS, 256, SMEM_F>>>(p_p3, Wl + 3 * DD * DD, p_acc,
                                               b3, p_Whi + 12L * DD * DD, bf, out);
        }
    }
}